// round 16
// baseline (speedup 1.0000x reference)
#include <cuda_runtime.h>
#include <cuda_fp16.h>
#include <cstdint>

#define BB 8
#define NN 1024
#define CC 256
#define HH 8
#define HD 32
#define TABLE 10

// Scratch (allocation-free rule: __device__ globals)
__device__ __half   g_ah [BB*NN*CC];      // X fp16 [8192][256]
__device__ __half   g_wq [3*CC*CC];       // W_qkv fp16 [256][768]  (raw layout)
__device__ __half   g_wp [CC*CC];         // W_proj fp16 [256][256] (raw layout)
__device__ __half   g_qh [BB*HH*NN*HD];   // q * scale * log2e, fp16
__device__ __half   g_kh [BB*HH*NN*HD];
__device__ __half   g_vh [BB*HH*NN*HD];
__device__ __half   g_xh [BB*NN*CC];      // attention output fp16 [8192][256]
__device__ uint8_t  g_rpn[BB*NN*NN/2];    // rp nibble-packed, bytes permuted t*4+nt

// ---------------------------------------------------------------------------
// helpers
// ---------------------------------------------------------------------------
__device__ __forceinline__ void mma_f16(float* c, const uint32_t* a, const uint32_t* b) {
    asm volatile(
        "mma.sync.aligned.m16n8k16.row.col.f32.f16.f16.f32 "
        "{%0,%1,%2,%3},{%4,%5,%6,%7},{%8,%9},{%0,%1,%2,%3};\n"
        : "+f"(c[0]), "+f"(c[1]), "+f"(c[2]), "+f"(c[3])
        : "r"(a[0]), "r"(a[1]), "r"(a[2]), "r"(a[3]), "r"(b[0]), "r"(b[1]));
}
__device__ __forceinline__ void ldsm4(uint32_t* r, uint32_t addr) {
    asm volatile("ldmatrix.sync.aligned.m8n8.x4.shared.b16 {%0,%1,%2,%3},[%4];"
                 : "=r"(r[0]), "=r"(r[1]), "=r"(r[2]), "=r"(r[3]) : "r"(addr));
}
__device__ __forceinline__ void ldsm4t(uint32_t* r, uint32_t addr) {
    asm volatile("ldmatrix.sync.aligned.m8n8.x4.trans.shared.b16 {%0,%1,%2,%3},[%4];"
                 : "=r"(r[0]), "=r"(r[1]), "=r"(r[2]), "=r"(r[3]) : "r"(addr));
}
__device__ __forceinline__ uint32_t smem_u32(const void* p) {
    uint32_t a;
    asm("{ .reg .u64 t; cvta.to.shared.u64 t, %1; cvt.u32.u64 %0, t; }" : "=r"(a) : "l"(p));
    return a;
}
__device__ __forceinline__ void cp16(uint32_t dst, const void* src) {
    asm volatile("cp.async.ca.shared.global [%0],[%1],16;" :: "r"(dst), "l"(src));
}
__device__ __forceinline__ void cp_commit() { asm volatile("cp.async.commit_group;"); }
__device__ __forceinline__ void cp_wait0()  { asm volatile("cp.async.wait_group 0;"); }
__device__ __forceinline__ uint32_t ex2h2(uint32_t x) {
    uint32_t r;
    asm("ex2.approx.f16x2 %0, %1;" : "=r"(r) : "r"(x));
    return r;
}
__device__ __forceinline__ uint32_t hadd2u(uint32_t a, uint32_t b) {
    __half2 r = __hadd2(*(__half2*)&a, *(__half2*)&b);
    return *(uint32_t*)&r;
}
__device__ __forceinline__ uint32_t pack2(float lo, float hi) {
    __half2 h = __floats2half2_rn(lo, hi);
    return *(uint32_t*)&h;
}

// ---------------------------------------------------------------------------
// Fused prep: X->fp16, Wqkv->fp16, Wproj->fp16, rp nibble-pack (permuted).
// ---------------------------------------------------------------------------
#define PREP_X  262144
#define PREP_WQ (PREP_X + 24576)
#define PREP_WP (PREP_WQ + 8192)
#define PREP_RP (PREP_WP + 262144)
#define PREP_BLOCKS ((PREP_RP + 255) / 256)

__global__ void __launch_bounds__(256) prep_kernel(
    const float4* __restrict__ X, const float4* __restrict__ Wq,
    const float4* __restrict__ Wp, const int4* __restrict__ rp)
{
    int idx = blockIdx.x * 256 + threadIdx.x;
    if (idx < PREP_WP) {
        const float4* src;
        uint4* dst;
        int i;
        if (idx < PREP_X)       { src = X;  dst = (uint4*)g_ah; i = idx; }
        else if (idx < PREP_WQ) { src = Wq; dst = (uint4*)g_wq; i = idx - PREP_X; }
        else                    { src = Wp; dst = (uint4*)g_wp; i = idx - PREP_WQ; }
        float4 a = src[i * 2], b = src[i * 2 + 1];
        __half2 h0 = __floats2half2_rn(a.x, a.y);
        __half2 h1 = __floats2half2_rn(a.z, a.w);
        __half2 h2 = __floats2half2_rn(b.x, b.y);
        __half2 h3 = __floats2half2_rn(b.z, b.w);
        dst[i] = make_uint4(*(uint32_t*)&h0, *(uint32_t*)&h1,
                            *(uint32_t*)&h2, *(uint32_t*)&h3);
    } else if (idx < PREP_RP) {
        int gI = idx - PREP_WP;
        int r[32];
        #pragma unroll
        for (int i = 0; i < 8; i++) {
            int4 v = rp[gI * 8 + i];
            r[i*4+0] = v.x; r[i*4+1] = v.y; r[i*4+2] = v.z; r[i*4+3] = v.w;
        }
        uint32_t w[4];
        #pragma unroll
        for (int t = 0; t < 4; t++) {
            uint32_t acc = 0;
            #pragma unroll
            for (int nt = 0; nt < 4; nt++) {
                uint32_t pair = (uint32_t)r[8*nt + 2*t] | ((uint32_t)r[8*nt + 2*t + 1] << 4);
                acc |= pair << (8 * nt);
            }
            w[t] = acc;
        }
        ((uint4*)g_rpn)[gI] = make_uint4(w[0], w[1], w[2], w[3]);
    }
}

// ---------------------------------------------------------------------------
// fp16 tensor-core GEMM (qkv): C[M,768] = A[M,256] @ W[256,768]
// block tile 64x128, K-chunks of 64, cp.async double buffer. 8 warps (2x4).
// ---------------------------------------------------------------------------
#define A_ROWB 144
#define B_ROWB 272
#define A_TILEB (64 * A_ROWB)            // 9216
#define B_TILEB (64 * B_ROWB)            // 17408
#define G_BUFB  (A_TILEB + B_TILEB)      // 26624
#define GEMM_SMEM (2 * G_BUFB)           // 53248

__global__ void __launch_bounds__(256) qkv_gemm_kernel(
    const uint4* __restrict__ A4, const __half* __restrict__ Bh)
{
    extern __shared__ char smem[];
    const int tid  = threadIdx.x;
    const int warp = tid >> 5, lane = tid & 31;
    const int g = lane >> 2, t = lane & 3;
    const int m0 = blockIdx.y * 64, n0 = blockIdx.x * 128;
    const int wm = warp >> 2, wn = warp & 3;
    const uint32_t sb = smem_u32(smem);
    const int arow = lane & 15, chi = lane >> 4;
    const int ldb = 768;

    float acc[2][4][4];
    #pragma unroll
    for (int mt = 0; mt < 2; mt++)
        #pragma unroll
        for (int nt = 0; nt < 4; nt++)
            #pragma unroll
            for (int r = 0; r < 4; r++) acc[mt][nt][r] = 0.f;

    auto load_chunk = [&](int c, int buf) {
        uint32_t base = sb + buf * G_BUFB;
        #pragma unroll
        for (int i = 0; i < 2; i++) {
            int idx = i * 256 + tid;
            int row = idx >> 3, cc = idx & 7;
            cp16(base + row * A_ROWB + cc * 16,
                 &A4[(long)(m0 + row) * 32 + c * 8 + cc]);
        }
        #pragma unroll
        for (int i = 0; i < 4; i++) {
            int idx = i * 256 + tid;
            int row = idx >> 4, cc = idx & 15;
            cp16(base + A_TILEB + row * B_ROWB + cc * 16,
                 Bh + (long)(c * 64 + row) * ldb + n0 + cc * 8);
        }
        cp_commit();
    };

    load_chunk(0, 0);

    for (int c = 0; c < 4; c++) {
        cp_wait0();
        __syncthreads();
        if (c < 3) load_chunk(c + 1, (c + 1) & 1);
        const uint32_t base = sb + (c & 1) * G_BUFB;
        const uint32_t bbase = base + A_TILEB;

        #pragma unroll
        for (int ks2 = 0; ks2 < 2; ks2++) {
            uint32_t bt[4][4];
            #pragma unroll
            for (int oct = 0; oct < 4; oct++)
                ldsm4t(bt[oct], bbase + (uint32_t)((ks2 * 32 + lane) * B_ROWB
                                                   + wn * 64 + oct * 16));
            #pragma unroll
            for (int r = 0; r < 2; r++) {
                uint32_t af[2][4];
                int s = ks2 * 2 + r;
                #pragma unroll
                for (int mt = 0; mt < 2; mt++)
                    ldsm4(af[mt], base + (uint32_t)((wm * 32 + mt * 16 + arow) * A_ROWB
                                                    + (2 * s + chi) * 16));
                #pragma unroll
                for (int mt = 0; mt < 2; mt++)
                    #pragma unroll
                    for (int nt = 0; nt < 4; nt++) {
                        uint32_t bb[2] = { bt[nt][2 * r], bt[nt][2 * r + 1] };
                        mma_f16(acc[mt][nt], af[mt], bb);
                    }
            }
        }
        __syncthreads();
    }

    const float scale = 0.25503483f;   // 32^-0.5 * log2(e)
    #pragma unroll
    for (int mt = 0; mt < 2; mt++) {
        int m = m0 + wm * 32 + mt * 16 + g;
        int bb = m >> 10, nn = m & 1023;
        #pragma unroll
        for (int nt = 0; nt < 4; nt++) {
            int col = n0 + wn * 32 + nt * 8 + 2 * t;
            int sel = col >> 8, hh = (col >> 5) & 7, dd = col & 31;
            float c0 = acc[mt][nt][0], c1 = acc[mt][nt][1];
            float c2 = acc[mt][nt][2], c3 = acc[mt][nt][3];
            if (sel == 0) { c0 *= scale; c1 *= scale; c2 *= scale; c3 *= scale; }
            __half* dst = (sel == 0) ? g_qh : (sel == 1) ? g_kh : g_vh;
            long base = (((long)bb * HH + hh) * NN + nn) * HD + dd;
            *(__half2*)&dst[base]           = __floats2half2_rn(c0, c1);
            *(__half2*)&dst[base + 8 * HD]  = __floats2half2_rn(c2, c3);
        }
    }
}

// ---------------------------------------------------------------------------
// proj GEMM: out[M,256] = Xh[M,256] @ Wp[256,256] + bias, fp32 out.
// 64x64 tiles, grid (4,128)=512 blocks; warps 4x2, warp tile 16x32.
// ---------------------------------------------------------------------------
#define PB_ROWB 144                      // 64 halves + pad
#define PB_TILEB (64 * PB_ROWB)          // 9216
#define PG_BUFB (A_TILEB + PB_TILEB)     // 18432
#define PROJ_SMEM (2 * PG_BUFB)          // 36864

__global__ void __launch_bounds__(256) proj_gemm_kernel(
    const uint4* __restrict__ A4, const __half* __restrict__ Bh,
    float* __restrict__ outp, const float* __restrict__ bias)
{
    extern __shared__ char smem[];
    const int tid  = threadIdx.x;
    const int warp = tid >> 5, lane = tid & 31;
    const int g = lane >> 2, t = lane & 3;
    const int m0 = blockIdx.y * 64, n0 = blockIdx.x * 64;
    const int wm = warp >> 1, wn = warp & 1;     // 4x2 warps: 16 rows x 32 cols
    const uint32_t sb = smem_u32(smem);
    const int arow = lane & 15, chi = lane >> 4;
    const int ldb = 256;

    float acc[4][4];
    #pragma unroll
    for (int nt = 0; nt < 4; nt++)
        #pragma unroll
        for (int r = 0; r < 4; r++) acc[nt][r] = 0.f;

    auto load_chunk = [&](int c, int buf) {
        uint32_t base = sb + buf * PG_BUFB;
        #pragma unroll
        for (int i = 0; i < 2; i++) {           // A: 512 cp16 (64 rows x 8)
            int idx = i * 256 + tid;
            int row = idx >> 3, cc = idx & 7;
            cp16(base + row * A_ROWB + cc * 16,
                 &A4[(long)(m0 + row) * 32 + c * 8 + cc]);
        }
        #pragma unroll
        for (int i = 0; i < 2; i++) {           // B: 512 cp16 (64 rows x 8)
            int idx = i * 256 + tid;
            int row = idx >> 3, cc = idx & 7;
            cp16(base + A_TILEB + row * PB_ROWB + cc * 16,
                 Bh + (long)(c * 64 + row) * ldb + n0 + cc * 8);
        }
        cp_commit();
    };

    load_chunk(0, 0);

    for (int c = 0; c < 4; c++) {
        cp_wait0();
        __syncthreads();
        if (c < 3) load_chunk(c + 1, (c + 1) & 1);
        const uint32_t base = sb + (c & 1) * PG_BUFB;
        const uint32_t bbase = base + A_TILEB;

        #pragma unroll
        for (int ks2 = 0; ks2 < 2; ks2++) {
            uint32_t bt[4][4];
            #pragma unroll
            for (int oct = 0; oct < 4; oct++)
                ldsm4t(bt[oct], bbase + (uint32_t)((ks2 * 32 + lane) * PB_ROWB
                                                   + wn * 64 + oct * 16));
            #pragma unroll
            for (int r = 0; r < 2; r++) {
                uint32_t af[4];
                int s = ks2 * 2 + r;
                ldsm4(af, base + (uint32_t)((wm * 16 + arow) * A_ROWB
                                            + (2 * s + chi) * 16));
                #pragma unroll
                for (int nt = 0; nt < 4; nt++) {
                    uint32_t bb[2] = { bt[nt][2 * r], bt[nt][2 * r + 1] };
                    mma_f16(acc[nt], af, bb);
                }
            }
        }
        __syncthreads();
    }

    {
        int m = m0 + wm * 16 + g;
        #pragma unroll
        for (int nt = 0; nt < 4; nt++) {
            int col = n0 + wn * 32 + nt * 8 + 2 * t;
            float b0 = bias[col], b1 = bias[col + 1];
            *(float2*)&outp[(long)m * 256 + col] =
                make_float2(acc[nt][0] + b0, acc[nt][1] + b1);
            *(float2*)&outp[(long)(m + 8) * 256 + col] =
                make_float2(acc[nt][2] + b0, acc[nt][3] + b1);
        }
    }
}

// ---------------------------------------------------------------------------
// Fused flash attention (exact R12 config): block = (batch, head, 128 q-rows),
// grid 512 (single wave at occ 4). 4 warps x 32 rows (2 m-tiles per warp);
// K/V frags loaded once per warp-tile and reused by both m-tiles. 32-key
// stages, cp.async double buffer. Fixed-shift ex2 softmax, ones-column sums.
// ---------------------------------------------------------------------------
#define AKROWB 80
#define AKTILE (32 * AKROWB)             // 2560
#define ARPB   2048                      // 128 rows x 16 B rpn slice
#define ASTAGE (2 * AKTILE + ARPB)       // 7168
#define ATT_SMEM (2 * ASTAGE + 640)      // 14976
#define SOFT_SHIFT 4.0f

__global__ void __launch_bounds__(128, 4) attn_mma_kernel(
    const int* __restrict__ rel_len, const float* __restrict__ bias_table)
{
    extern __shared__ char smc[];
    const uint32_t sb = smem_u32(smc);

    const int tid  = threadIdx.x;
    const int w    = tid >> 5;               // warp 0..3 -> 32-row span
    const int lane = tid & 31;
    const int g    = lane >> 2;
    const int t    = lane & 3;
    const int b     = blockIdx.x >> 6;
    const int h     = (blockIdx.x >> 3) & 7;
    const int chunk = blockIdx.x & 7;
    const int row0  = chunk * 128;

    uint32_t* tblp = (uint32_t*)(smc + 2 * ASTAGE);

    // per-head masked bias pair table (log2 domain)
    {
        const int mask_len = (int)(__int2float_rn(rel_len[b]) * 0.5f);
        for (int i = tid; i < 160; i += 128) {
            int lo = i & 15, hi = i >> 4;
            float vlo = (lo < TABLE)
                ? bias_table[lo * HH + h] * 1.4426950408889634f
                  + ((lo > mask_len) ? -144.2695040888963f : 0.f) : 0.f;
            float vhi = bias_table[hi * HH + h] * 1.4426950408889634f
                  + ((hi > mask_len) ? -144.2695040888963f : 0.f);
            tblp[i] = pack2(vlo, vhi);
        }
    }
    // V pad columns (d=32..39) = fp16 ones, both stages
    if (tid < 64) {
        const uint4 ones = make_uint4(0x3C003C00u, 0x3C003C00u, 0x3C003C00u, 0x3C003C00u);
        int stg = tid >> 5, row = tid & 31;
        *(uint4*)(smc + stg * ASTAGE + AKTILE + row * AKROWB + 64) = ones;
    }

    // Q fragments: warp w's 32 rows (2 m-tiles), scale*log2e pre-folded
    uint32_t qa[2][2][4];
    {
        const uint32_t* qw = (const uint32_t*)g_qh;
        long rbase = ((long)(b * HH) + h) * NN + row0 + w * 32;
        #pragma unroll
        for (int mt = 0; mt < 2; mt++) {
            long rA = (rbase + mt * 16 + g) * 16, rB = rA + 128;
            #pragma unroll
            for (int ks = 0; ks < 2; ks++) {
                int wd = ks * 8 + t;
                qa[mt][ks][0] = qw[rA + wd];
                qa[mt][ks][1] = qw[rB + wd];
                qa[mt][ks][2] = qw[rA + wd + 4];
                qa[mt][ks][3] = qw[rB + wd + 4];
            }
        }
    }

    float o[2][5][4];                        // nt=4 is ones column (row sums)
    #pragma unroll
    for (int mt = 0; mt < 2; mt++)
        #pragma unroll
        for (int nt = 0; nt < 5; nt++)
            #pragma unroll
            for (int r = 0; r < 4; r++) o[mt][nt][r] = 0.f;

    const __half*  gk   = g_kh;
    const __half*  gv   = g_vh;
    const uint8_t* grpn = g_rpn;
    const long kvhead = ((long)(b * HH) + h) * NN * HD;
    const long rpnrow = ((long)b * NN + row0) * (NN / 2);

    // cooperative prefetch of tile j into stage stg (128 threads)
    auto prefetch = [&](int j, int stg) {
        uint32_t base = sb + stg * ASTAGE;
        long src = kvhead + (long)(j * 32) * HD;
        int row = tid >> 2, ch = tid & 3;
        uint32_t d = base + row * AKROWB + ch * 16;
        cp16(d, gk + src + row * HD + ch * 8);
        cp16(d + AKTILE, gv + src + row * HD + ch * 8);
        // rpn: 128 rows x 16 B for this key tile
        cp16(base + 2 * AKTILE + tid * 16, grpn + rpnrow + (long)tid * 512 + j * 16);
        cp_commit();
    };

    prefetch(0, 0);

    const int ln8 = lane & 7, l8 = lane >> 3;

    for (int j = 0; j < 32; j++) {
        const int stg = j & 1;
        cp_wait0();
        __syncthreads();                     // stage stg ready; stage stg^1 free
        if (j < 31) prefetch(j + 1, stg ^ 1);

        const uint32_t kbase = sb + stg * ASTAGE;
        const uint32_t vbase = kbase + AKTILE;
        const char*    rpn_s = smc + stg * ASTAGE + 2 * AKTILE;

        // ---- K frags once, S for both m-tiles (acc preloaded with -SHIFT) ----
        float c[2][4][4];
        #pragma unroll
        for (int mt = 0; mt < 2; mt++)
            #pragma unroll
            for (int nt = 0; nt < 4; nt++)
                #pragma unroll
                for (int r = 0; r < 4; r++) c[mt][nt][r] = -SOFT_SHIFT;
        {
            uint32_t kb[4][4];
            uint32_t ka = kbase + (uint32_t)(ln8 * AKROWB + l8 * 16);
            #pragma unroll
            for (int nt = 0; nt < 4; nt++)
                ldsm4(kb[nt], ka + nt * (8 * AKROWB));
            #pragma unroll
            for (int nt = 0; nt < 4; nt++)
                #pragma unroll
                for (int ks = 0; ks < 2; ks++) {
                    uint32_t bf[2] = { kb[nt][2 * ks], kb[nt][2 * ks + 1] };
                    mma_f16(c[0][nt], qa[0][ks], bf);
                    mma_f16(c[1][nt], qa[1][ks], bf);
                }
        }

        // ---- V frags once (shared by both m-tiles) ----
        uint32_t vb[5][4];
        {
            uint32_t va = vbase + (uint32_t)(lane * AKROWB);
            #pragma unroll
            for (int nt = 0; nt < 5; nt++)
                ldsm4t(vb[nt], va + nt * 16);
        }

        // ---- bias + fixed-shift ex2 softmax -> P A-frags, then PV ----
        #pragma unroll
        for (int mt = 0; mt < 2; mt++) {
            int rAr = w * 32 + mt * 16 + g;
            uint32_t wA = *(const uint32_t*)(rpn_s + rAr * 16 + t * 4);
            uint32_t wB = *(const uint32_t*)(rpn_s + (rAr + 8) * 16 + t * 4);
            uint32_t hA[4], hB[4];
            #pragma unroll
            for (int nt = 0; nt < 4; nt++) {
                uint32_t iA = (wA >> (8 * nt)) & 0xFF;
                uint32_t iB = (wB >> (8 * nt)) & 0xFF;
                hA[nt] = ex2h2(hadd2u(pack2(c[mt][nt][0], c[mt][nt][1]), tblp[iA]));
                hB[nt] = ex2h2(hadd2u(pack2(c[mt][nt][2], c[mt][nt][3]), tblp[iB]));
            }
            uint32_t pa[2][4];
            #pragma unroll
            for (int ks = 0; ks < 2; ks++) {
                pa[ks][0] = hA[2 * ks];
                pa[ks][1] = hB[2 * ks];
                pa[ks][2] = hA[2 * ks + 1];
                pa[ks][3] = hB[2 * ks + 1];
            }
            #pragma unroll
            for (int ks = 0; ks < 2; ks++)
                #pragma unroll
                for (int nt = 0; nt < 5; nt++) {
                    uint32_t bf[2] = { vb[nt][2 * ks], vb[nt][2 * ks + 1] };
                    mma_f16(o[mt][nt], pa[ks], bf);
                }
        }
    }

    // ---- epilogue: normalize by ones-column sums, store fp16 to g_xh ----
    #pragma unroll
    for (int mt = 0; mt < 2; mt++) {
        float i0 = 1.f / o[mt][4][0];
        float i1 = 1.f / o[mt][4][2];
        int rA = row0 + w * 32 + mt * 16 + g;
        #pragma unroll
        for (int nt = 0; nt < 4; nt++) {
            int col = h * HD + nt * 8 + 2 * t;
            *(__half2*)&g_xh[((long)b * NN + rA) * CC + col] =
                __floats2half2_rn(o[mt][nt][0] * i0, o[mt][nt][1] * i0);
            *(__half2*)&g_xh[((long)b * NN + rA + 8) * CC + col] =
                __floats2half2_rn(o[mt][nt][2] * i1, o[mt][nt][3] * i1);
        }
    }
}

// ---------------------------------------------------------------------------
extern "C" void kernel_launch(void* const* d_in, const int* in_sizes, int n_in,
                              void* d_out, int out_size)
{
    const float* X       = (const float*)d_in[0];
    const int*   rp      = (const int*)  d_in[1];
    const int*   rel_len = (const int*)  d_in[2];
    const float* Wqkv    = (const float*)d_in[3];
    const float* Wproj   = (const float*)d_in[4];
    const float* bproj   = (const float*)d_in[5];
    const float* btab    = (const float*)d_in[6];
    float* out = (float*)d_out;

    __half* d_ah;  cudaGetSymbolAddress((void**)&d_ah, g_ah);
    __half* d_wq;  cudaGetSymbolAddress((void**)&d_wq, g_wq);
    __half* d_wp;  cudaGetSymbolAddress((void**)&d_wp, g_wp);
    __half* d_xh;  cudaGetSymbolAddress((void**)&d_xh, g_xh);

    // 1) fused prep: converts + rp nibble pack
    prep_kernel<<<PREP_BLOCKS, 256>>>((const float4*)X, (const float4*)Wqkv,
                                      (const float4*)Wproj, (const int4*)rp);

    // 2) qkv GEMM (64x128 tiles, 768 blocks)
    cudaFuncSetAttribute(qkv_gemm_kernel,
                         cudaFuncAttributeMaxDynamicSharedMemorySize, GEMM_SMEM);
    qkv_gemm_kernel<<<dim3(6, 128), 256, GEMM_SMEM>>>((const uint4*)d_ah, d_wq);

    // 3) attention (512 blocks x 128 threads, single wave, occ 4) — R12 config
    attn_mma_kernel<<<BB * HH * 8, 128, ATT_SMEM>>>(rel_len, btab);

    // 4) proj GEMM (64x64 tiles, 512 blocks) + bias -> fp32 out
    proj_gemm_kernel<<<dim3(4, 128), 256, PROJ_SMEM>>>(
        (const uint4*)d_xh, d_wp, out, bproj);
}

// round 17
// speedup vs baseline: 1.0249x; 1.0249x over previous
#include <cuda_runtime.h>
#include <cuda_fp16.h>
#include <cstdint>

#define BB 8
#define NN 1024
#define CC 256
#define HH 8
#define HD 32
#define TABLE 10

// Scratch (allocation-free rule: __device__ globals)
__device__ __half   g_ah [BB*NN*CC];      // X fp16 [8192][256]
__device__ __half   g_wq [3*CC*CC];       // W_qkv fp16 [256][768]  (raw layout)
__device__ __half   g_wp [CC*CC];         // W_proj fp16 [256][256] (raw layout)
__device__ __half   g_qh [BB*HH*NN*HD];   // q * scale * log2e, fp16
__device__ __half   g_kh [BB*HH*NN*HD];
__device__ __half   g_vh [BB*HH*NN*HD];
__device__ __half   g_xh [BB*NN*CC];      // attention output fp16 [8192][256]
__device__ uint8_t  g_rpn[BB*NN*NN/2];    // rp nibble-packed, bytes permuted t*4+nt

// ---------------------------------------------------------------------------
// helpers
// ---------------------------------------------------------------------------
__device__ __forceinline__ void mma_f16(float* c, const uint32_t* a, const uint32_t* b) {
    asm volatile(
        "mma.sync.aligned.m16n8k16.row.col.f32.f16.f16.f32 "
        "{%0,%1,%2,%3},{%4,%5,%6,%7},{%8,%9},{%0,%1,%2,%3};\n"
        : "+f"(c[0]), "+f"(c[1]), "+f"(c[2]), "+f"(c[3])
        : "r"(a[0]), "r"(a[1]), "r"(a[2]), "r"(a[3]), "r"(b[0]), "r"(b[1]));
}
__device__ __forceinline__ void ldsm4(uint32_t* r, uint32_t addr) {
    asm volatile("ldmatrix.sync.aligned.m8n8.x4.shared.b16 {%0,%1,%2,%3},[%4];"
                 : "=r"(r[0]), "=r"(r[1]), "=r"(r[2]), "=r"(r[3]) : "r"(addr));
}
__device__ __forceinline__ void ldsm4t(uint32_t* r, uint32_t addr) {
    asm volatile("ldmatrix.sync.aligned.m8n8.x4.trans.shared.b16 {%0,%1,%2,%3},[%4];"
                 : "=r"(r[0]), "=r"(r[1]), "=r"(r[2]), "=r"(r[3]) : "r"(addr));
}
__device__ __forceinline__ uint32_t smem_u32(const void* p) {
    uint32_t a;
    asm("{ .reg .u64 t; cvta.to.shared.u64 t, %1; cvt.u32.u64 %0, t; }" : "=r"(a) : "l"(p));
    return a;
}
__device__ __forceinline__ void cp16(uint32_t dst, const void* src) {
    asm volatile("cp.async.ca.shared.global [%0],[%1],16;" :: "r"(dst), "l"(src));
}
__device__ __forceinline__ void cp_commit() { asm volatile("cp.async.commit_group;"); }
__device__ __forceinline__ void cp_wait0()  { asm volatile("cp.async.wait_group 0;"); }
__device__ __forceinline__ uint32_t ex2h2(uint32_t x) {
    uint32_t r;
    asm("ex2.approx.f16x2 %0, %1;" : "=r"(r) : "r"(x));
    return r;
}
__device__ __forceinline__ uint32_t hadd2u(uint32_t a, uint32_t b) {
    __half2 r = __hadd2(*(__half2*)&a, *(__half2*)&b);
    return *(uint32_t*)&r;
}
__device__ __forceinline__ uint32_t pack2(float lo, float hi) {
    __half2 h = __floats2half2_rn(lo, hi);
    return *(uint32_t*)&h;
}

// ---------------------------------------------------------------------------
// Fused prep: X->fp16, Wqkv->fp16, Wproj->fp16, rp nibble-pack (permuted).
// ---------------------------------------------------------------------------
#define PREP_X  262144
#define PREP_WQ (PREP_X + 24576)
#define PREP_WP (PREP_WQ + 8192)
#define PREP_RP (PREP_WP + 262144)
#define PREP_BLOCKS ((PREP_RP + 255) / 256)

__global__ void __launch_bounds__(256) prep_kernel(
    const float4* __restrict__ X, const float4* __restrict__ Wq,
    const float4* __restrict__ Wp, const int4* __restrict__ rp)
{
    int idx = blockIdx.x * 256 + threadIdx.x;
    if (idx < PREP_WP) {
        const float4* src;
        uint4* dst;
        int i;
        if (idx < PREP_X)       { src = X;  dst = (uint4*)g_ah; i = idx; }
        else if (idx < PREP_WQ) { src = Wq; dst = (uint4*)g_wq; i = idx - PREP_X; }
        else                    { src = Wp; dst = (uint4*)g_wp; i = idx - PREP_WQ; }
        float4 a = src[i * 2], b = src[i * 2 + 1];
        __half2 h0 = __floats2half2_rn(a.x, a.y);
        __half2 h1 = __floats2half2_rn(a.z, a.w);
        __half2 h2 = __floats2half2_rn(b.x, b.y);
        __half2 h3 = __floats2half2_rn(b.z, b.w);
        dst[i] = make_uint4(*(uint32_t*)&h0, *(uint32_t*)&h1,
                            *(uint32_t*)&h2, *(uint32_t*)&h3);
    } else if (idx < PREP_RP) {
        int gI = idx - PREP_WP;
        int r[32];
        #pragma unroll
        for (int i = 0; i < 8; i++) {
            int4 v = rp[gI * 8 + i];
            r[i*4+0] = v.x; r[i*4+1] = v.y; r[i*4+2] = v.z; r[i*4+3] = v.w;
        }
        uint32_t w[4];
        #pragma unroll
        for (int t = 0; t < 4; t++) {
            uint32_t acc = 0;
            #pragma unroll
            for (int nt = 0; nt < 4; nt++) {
                uint32_t pair = (uint32_t)r[8*nt + 2*t] | ((uint32_t)r[8*nt + 2*t + 1] << 4);
                acc |= pair << (8 * nt);
            }
            w[t] = acc;
        }
        ((uint4*)g_rpn)[gI] = make_uint4(w[0], w[1], w[2], w[3]);
    }
}

// ---------------------------------------------------------------------------
// fp16 tensor-core GEMM: C[M,N] = A[M,256] @ W[256,N]
// block tile 64x128, K-chunks of 64, cp.async double buffer. 8 warps (2x4),
// warp tile 32x32.
// ---------------------------------------------------------------------------
#define A_ROWB 144
#define B_ROWB 272
#define A_TILEB (64 * A_ROWB)            // 9216
#define B_TILEB (64 * B_ROWB)            // 17408
#define G_BUFB  (A_TILEB + B_TILEB)      // 26624
#define GEMM_SMEM (2 * G_BUFB)           // 53248

template<bool PROJ>
__global__ void __launch_bounds__(256) gemm_f16_kernel(
    const uint4* __restrict__ A4, const __half* __restrict__ Bh, int ldb,
    float* __restrict__ outp, const float* __restrict__ bias)
{
    extern __shared__ char smem[];
    const int tid  = threadIdx.x;
    const int warp = tid >> 5, lane = tid & 31;
    const int g = lane >> 2, t = lane & 3;
    const int m0 = blockIdx.y * 64, n0 = blockIdx.x * 128;
    const int wm = warp >> 2, wn = warp & 3;
    const uint32_t sb = smem_u32(smem);
    const int arow = lane & 15, chi = lane >> 4;

    float acc[2][4][4];
    #pragma unroll
    for (int mt = 0; mt < 2; mt++)
        #pragma unroll
        for (int nt = 0; nt < 4; nt++)
            #pragma unroll
            for (int r = 0; r < 4; r++) acc[mt][nt][r] = 0.f;

    auto load_chunk = [&](int c, int buf) {
        uint32_t base = sb + buf * G_BUFB;
        #pragma unroll
        for (int i = 0; i < 2; i++) {
            int idx = i * 256 + tid;
            int row = idx >> 3, cc = idx & 7;
            cp16(base + row * A_ROWB + cc * 16,
                 &A4[(long)(m0 + row) * 32 + c * 8 + cc]);
        }
        #pragma unroll
        for (int i = 0; i < 4; i++) {
            int idx = i * 256 + tid;
            int row = idx >> 4, cc = idx & 15;
            cp16(base + A_TILEB + row * B_ROWB + cc * 16,
                 Bh + (long)(c * 64 + row) * ldb + n0 + cc * 8);
        }
        cp_commit();
    };

    load_chunk(0, 0);

    for (int c = 0; c < 4; c++) {
        cp_wait0();
        __syncthreads();
        if (c < 3) load_chunk(c + 1, (c + 1) & 1);
        const uint32_t base = sb + (c & 1) * G_BUFB;
        const uint32_t bbase = base + A_TILEB;

        #pragma unroll
        for (int ks2 = 0; ks2 < 2; ks2++) {
            uint32_t bt[4][4];
            #pragma unroll
            for (int oct = 0; oct < 4; oct++)
                ldsm4t(bt[oct], bbase + (uint32_t)((ks2 * 32 + lane) * B_ROWB
                                                   + wn * 64 + oct * 16));
            #pragma unroll
            for (int r = 0; r < 2; r++) {
                uint32_t af[2][4];
                int s = ks2 * 2 + r;
                #pragma unroll
                for (int mt = 0; mt < 2; mt++)
                    ldsm4(af[mt], base + (uint32_t)((wm * 32 + mt * 16 + arow) * A_ROWB
                                                    + (2 * s + chi) * 16));
                #pragma unroll
                for (int mt = 0; mt < 2; mt++)
                    #pragma unroll
                    for (int nt = 0; nt < 4; nt++) {
                        uint32_t bb[2] = { bt[nt][2 * r], bt[nt][2 * r + 1] };
                        mma_f16(acc[mt][nt], af[mt], bb);
                    }
            }
        }
        __syncthreads();
    }

    if (PROJ) {
        #pragma unroll
        for (int mt = 0; mt < 2; mt++) {
            int m = m0 + wm * 32 + mt * 16 + g;
            #pragma unroll
            for (int nt = 0; nt < 4; nt++) {
                int col = n0 + wn * 32 + nt * 8 + 2 * t;
                float b0 = bias[col], b1 = bias[col + 1];
                *(float2*)&outp[(long)m * 256 + col] =
                    make_float2(acc[mt][nt][0] + b0, acc[mt][nt][1] + b1);
                *(float2*)&outp[(long)(m + 8) * 256 + col] =
                    make_float2(acc[mt][nt][2] + b0, acc[mt][nt][3] + b1);
            }
        }
    } else {
        const float scale = 0.25503483f;   // 32^-0.5 * log2(e)
        #pragma unroll
        for (int mt = 0; mt < 2; mt++) {
            int m = m0 + wm * 32 + mt * 16 + g;
            int bb = m >> 10, nn = m & 1023;
            #pragma unroll
            for (int nt = 0; nt < 4; nt++) {
                int col = n0 + wn * 32 + nt * 8 + 2 * t;
                int sel = col >> 8, hh = (col >> 5) & 7, dd = col & 31;
                float c0 = acc[mt][nt][0], c1 = acc[mt][nt][1];
                float c2 = acc[mt][nt][2], c3 = acc[mt][nt][3];
                if (sel == 0) { c0 *= scale; c1 *= scale; c2 *= scale; c3 *= scale; }
                __half* dst = (sel == 0) ? g_qh : (sel == 1) ? g_kh : g_vh;
                long base = (((long)bb * HH + hh) * NN + nn) * HD + dd;
                *(__half2*)&dst[base]           = __floats2half2_rn(c0, c1);
                *(__half2*)&dst[base + 8 * HD]  = __floats2half2_rn(c2, c3);
            }
        }
    }
}

// ---------------------------------------------------------------------------
// Fused flash attention v7 (R12 config): block = (batch, head, 128 q-rows),
// grid 512 (single wave at occ 4). 4 warps x 32 rows (2 m-tiles per warp);
// K/V frags loaded once per warp-tile and reused by both m-tiles. 32-key
// stages, cp.async double buffer. Fixed-shift ex2 softmax, ones-column sums.
// ---------------------------------------------------------------------------
#define AKROWB 80
#define AKTILE (32 * AKROWB)             // 2560
#define ARPB   2048                      // 128 rows x 16 B rpn slice
#define ASTAGE (2 * AKTILE + ARPB)       // 7168
#define ATT_SMEM (2 * ASTAGE + 640)      // 14976
#define SOFT_SHIFT 4.0f

__global__ void __launch_bounds__(128, 4) attn_mma_kernel(
    const int* __restrict__ rel_len, const float* __restrict__ bias_table)
{
    extern __shared__ char smc[];
    const uint32_t sb = smem_u32(smc);

    const int tid  = threadIdx.x;
    const int w    = tid >> 5;               // warp 0..3 -> 32-row span
    const int lane = tid & 31;
    const int g    = lane >> 2;
    const int t    = lane & 3;
    const int b     = blockIdx.x >> 6;
    const int h     = (blockIdx.x >> 3) & 7;
    const int chunk = blockIdx.x & 7;
    const int row0  = chunk * 128;

    uint32_t* tblp = (uint32_t*)(smc + 2 * ASTAGE);

    // per-head masked bias pair table (log2 domain)
    {
        const int mask_len = (int)(__int2float_rn(rel_len[b]) * 0.5f);
        for (int i = tid; i < 160; i += 128) {
            int lo = i & 15, hi = i >> 4;
            float vlo = (lo < TABLE)
                ? bias_table[lo * HH + h] * 1.4426950408889634f
                  + ((lo > mask_len) ? -144.2695040888963f : 0.f) : 0.f;
            float vhi = bias_table[hi * HH + h] * 1.4426950408889634f
                  + ((hi > mask_len) ? -144.2695040888963f : 0.f);
            tblp[i] = pack2(vlo, vhi);
        }
    }
    // V pad columns (d=32..39) = fp16 ones, both stages
    if (tid < 64) {
        const uint4 ones = make_uint4(0x3C003C00u, 0x3C003C00u, 0x3C003C00u, 0x3C003C00u);
        int stg = tid >> 5, row = tid & 31;
        *(uint4*)(smc + stg * ASTAGE + AKTILE + row * AKROWB + 64) = ones;
    }

    // Q fragments: warp w's 32 rows (2 m-tiles), scale*log2e pre-folded
    uint32_t qa[2][2][4];
    {
        const uint32_t* qw = (const uint32_t*)g_qh;
        long rbase = ((long)(b * HH) + h) * NN + row0 + w * 32;
        #pragma unroll
        for (int mt = 0; mt < 2; mt++) {
            long rA = (rbase + mt * 16 + g) * 16, rB = rA + 128;
            #pragma unroll
            for (int ks = 0; ks < 2; ks++) {
                int wd = ks * 8 + t;
                qa[mt][ks][0] = qw[rA + wd];
                qa[mt][ks][1] = qw[rB + wd];
                qa[mt][ks][2] = qw[rA + wd + 4];
                qa[mt][ks][3] = qw[rB + wd + 4];
            }
        }
    }

    float o[2][5][4];                        // nt=4 is ones column (row sums)
    #pragma unroll
    for (int mt = 0; mt < 2; mt++)
        #pragma unroll
        for (int nt = 0; nt < 5; nt++)
            #pragma unroll
            for (int r = 0; r < 4; r++) o[mt][nt][r] = 0.f;

    const __half*  gk   = g_kh;
    const __half*  gv   = g_vh;
    const uint8_t* grpn = g_rpn;
    const long kvhead = ((long)(b * HH) + h) * NN * HD;
    const long rpnrow = ((long)b * NN + row0) * (NN / 2);

    // cooperative prefetch of tile j into stage stg (128 threads)
    auto prefetch = [&](int j, int stg) {
        uint32_t base = sb + stg * ASTAGE;
        long src = kvhead + (long)(j * 32) * HD;
        int row = tid >> 2, ch = tid & 3;
        uint32_t d = base + row * AKROWB + ch * 16;
        cp16(d, gk + src + row * HD + ch * 8);
        cp16(d + AKTILE, gv + src + row * HD + ch * 8);
        // rpn: 128 rows x 16 B for this key tile
        cp16(base + 2 * AKTILE + tid * 16, grpn + rpnrow + (long)tid * 512 + j * 16);
        cp_commit();
    };

    prefetch(0, 0);

    const int ln8 = lane & 7, l8 = lane >> 3;

    for (int j = 0; j < 32; j++) {
        const int stg = j & 1;
        cp_wait0();
        __syncthreads();                     // stage stg ready; stage stg^1 free
        if (j < 31) prefetch(j + 1, stg ^ 1);

        const uint32_t kbase = sb + stg * ASTAGE;
        const uint32_t vbase = kbase + AKTILE;
        const char*    rpn_s = smc + stg * ASTAGE + 2 * AKTILE;

        // ---- K frags once, S for both m-tiles (acc preloaded with -SHIFT) ----
        float c[2][4][4];
        #pragma unroll
        for (int mt = 0; mt < 2; mt++)
            #pragma unroll
            for (int nt = 0; nt < 4; nt++)
                #pragma unroll
                for (int r = 0; r < 4; r++) c[mt][nt][r] = -SOFT_SHIFT;
        {
            uint32_t kb[4][4];
            uint32_t ka = kbase + (uint32_t)(ln8 * AKROWB + l8 * 16);
            #pragma unroll
            for (int nt = 0; nt < 4; nt++)
                ldsm4(kb[nt], ka + nt * (8 * AKROWB));
            #pragma unroll
            for (int nt = 0; nt < 4; nt++)
                #pragma unroll
                for (int ks = 0; ks < 2; ks++) {
                    uint32_t bf[2] = { kb[nt][2 * ks], kb[nt][2 * ks + 1] };
                    mma_f16(c[0][nt], qa[0][ks], bf);
                    mma_f16(c[1][nt], qa[1][ks], bf);
                }
        }

        // ---- V frags once (shared by both m-tiles) ----
        uint32_t vb[5][4];
        {
            uint32_t va = vbase + (uint32_t)(lane * AKROWB);
            #pragma unroll
            for (int nt = 0; nt < 5; nt++)
                ldsm4t(vb[nt], va + nt * 16);
        }

        // ---- bias + fixed-shift ex2 softmax -> P A-frags, then PV ----
        #pragma unroll
        for (int mt = 0; mt < 2; mt++) {
            int rAr = w * 32 + mt * 16 + g;
            uint32_t wA = *(const uint32_t*)(rpn_s + rAr * 16 + t * 4);
            uint32_t wB = *(const uint32_t*)(rpn_s + (rAr + 8) * 16 + t * 4);
            uint32_t hA[4], hB[4];
            #pragma unroll
            for (int nt = 0; nt < 4; nt++) {
                uint32_t iA = (wA >> (8 * nt)) & 0xFF;
                uint32_t iB = (wB >> (8 * nt)) & 0xFF;
                hA[nt] = ex2h2(hadd2u(pack2(c[mt][nt][0], c[mt][nt][1]), tblp[iA]));
                hB[nt] = ex2h2(hadd2u(pack2(c[mt][nt][2], c[mt][nt][3]), tblp[iB]));
            }
            uint32_t pa[2][4];
            #pragma unroll
            for (int ks = 0; ks < 2; ks++) {
                pa[ks][0] = hA[2 * ks];
                pa[ks][1] = hB[2 * ks];
                pa[ks][2] = hA[2 * ks + 1];
                pa[ks][3] = hB[2 * ks + 1];
            }
            #pragma unroll
            for (int ks = 0; ks < 2; ks++)
                #pragma unroll
                for (int nt = 0; nt < 5; nt++) {
                    uint32_t bf[2] = { vb[nt][2 * ks], vb[nt][2 * ks + 1] };
                    mma_f16(o[mt][nt], pa[ks], bf);
                }
        }
    }

    // ---- epilogue: normalize by ones-column sums, store fp16 to g_xh ----
    #pragma unroll
    for (int mt = 0; mt < 2; mt++) {
        float i0 = 1.f / o[mt][4][0];
        float i1 = 1.f / o[mt][4][2];
        int rA = row0 + w * 32 + mt * 16 + g;
        #pragma unroll
        for (int nt = 0; nt < 4; nt++) {
            int col = h * HD + nt * 8 + 2 * t;
            *(__half2*)&g_xh[((long)b * NN + rA) * CC + col] =
                __floats2half2_rn(o[mt][nt][0] * i0, o[mt][nt][1] * i0);
            *(__half2*)&g_xh[((long)b * NN + rA + 8) * CC + col] =
                __floats2half2_rn(o[mt][nt][2] * i1, o[mt][nt][3] * i1);
        }
    }
}

// ---------------------------------------------------------------------------
extern "C" void kernel_launch(void* const* d_in, const int* in_sizes, int n_in,
                              void* d_out, int out_size)
{
    const float* X       = (const float*)d_in[0];
    const int*   rp      = (const int*)  d_in[1];
    const int*   rel_len = (const int*)  d_in[2];
    const float* Wqkv    = (const float*)d_in[3];
    const float* Wproj   = (const float*)d_in[4];
    const float* bproj   = (const float*)d_in[5];
    const float* btab    = (const float*)d_in[6];
    float* out = (float*)d_out;

    __half* d_ah;  cudaGetSymbolAddress((void**)&d_ah, g_ah);
    __half* d_wq;  cudaGetSymbolAddress((void**)&d_wq, g_wq);
    __half* d_wp;  cudaGetSymbolAddress((void**)&d_wp, g_wp);
    __half* d_xh;  cudaGetSymbolAddress((void**)&d_xh, g_xh);

    // 1) fused prep: converts + rp nibble pack
    prep_kernel<<<PREP_BLOCKS, 256>>>((const float4*)X, (const float4*)Wqkv,
                                      (const float4*)Wproj, (const int4*)rp);

    // 2) qkv GEMM (64x128 tiles, 768 blocks)
    cudaFuncSetAttribute(gemm_f16_kernel<false>,
                         cudaFuncAttributeMaxDynamicSharedMemorySize, GEMM_SMEM);
    gemm_f16_kernel<false><<<dim3(6, 128), 256, GEMM_SMEM>>>(
        (const uint4*)d_ah, d_wq, 768, nullptr, nullptr);

    // 3) attention (512 blocks x 128 threads, single wave)
    attn_mma_kernel<<<BB * HH * 8, 128, ATT_SMEM>>>(rel_len, btab);

    // 4) proj GEMM (64x128 tiles, 256 blocks) + bias -> fp32 out
    cudaFuncSetAttribute(gemm_f16_kernel<true>,
                         cudaFuncAttributeMaxDynamicSharedMemorySize, GEMM_SMEM);
    gemm_f16_kernel<true><<<dim3(2, 128), 256, GEMM_SMEM>>>(
        (const uint4*)d_xh, d_wp, 256, out, bproj);
}